// round 6
// baseline (speedup 1.0000x reference)
#include <cuda_runtime.h>

#define N_NODES 100000
#define N_EDGES 1600000
#define N_PE    200000
#define F1 128
#define F2 8

// Scratch (static device globals — no allocation allowed)
__device__ __align__(16) float g_hs1[N_NODES * F1];   // dinv-scaled x@W1
__device__ __align__(16) float g_acc1[N_NODES * F1];  // edge-aggregated hs1
__device__ __align__(16) float g_hs2[N_NODES * F2];   // dinv-scaled h@W2
__device__ __align__(16) float g_acc2[N_NODES * F2];
__device__ __align__(16) float g_z[N_NODES * F2];     // layer-2 output
__device__ __align__(16) float g_dinv[N_NODES];
__device__ __align__(16) int   g_deg[N_NODES];

// ---------------------------------------------------------------------------
__global__ __launch_bounds__(256) void zero_kernel() {
    int idx = blockIdx.x * blockDim.x + threadIdx.x;
    int stride = gridDim.x * blockDim.x;
    float4 z4 = make_float4(0.f, 0.f, 0.f, 0.f);
    for (int i = idx; i < N_NODES * F1 / 4; i += stride) ((float4*)g_acc1)[i] = z4;
    for (int i = idx; i < N_NODES * F2 / 4; i += stride) ((float4*)g_acc2)[i] = z4;
    for (int i = idx; i < N_NODES / 4; i += stride) ((int4*)g_deg)[i] = make_int4(0, 0, 0, 0);
}

// Count in-degree over dst (self-loop +1 folded into dinv kernel)
__global__ __launch_bounds__(256) void deg_kernel(const int* __restrict__ dst) {
    int e = blockIdx.x * blockDim.x + threadIdx.x;
    if (e < N_EDGES) atomicAdd(&g_deg[dst[e]], 1);
}

__global__ __launch_bounds__(256) void dinv_kernel() {
    int i = blockIdx.x * blockDim.x + threadIdx.x;
    if (i < N_NODES) g_dinv[i] = rsqrtf((float)g_deg[i] + 1.0f);
}

// ---------------------------------------------------------------------------
// GEMM1: hs1[i,:] = dinv[i] * (x[i,:] @ W1)   (M=100000, K=256, N=128)
// 64x128 tile per block, 256 threads, 8x4 microtile, K-chunks of 16.
__global__ __launch_bounds__(256) void gemm1_kernel(const float* __restrict__ x,
                                                    const float* __restrict__ W1) {
    __shared__ float As[16][64];    // transposed A chunk
    __shared__ float Bs[16][128];
    const int tid  = threadIdx.x;
    const int tr   = tid >> 5;      // warp id = row group (8 rows each)
    const int tc   = tid & 31;      // col group (4 cols each)
    const int brow = blockIdx.x * 64;
    const int arow = tid >> 2;
    const int ak   = (tid & 3) << 2;
    const int grow = brow + arow;

    float acc[8][4];
#pragma unroll
    for (int r = 0; r < 8; r++)
#pragma unroll
        for (int c = 0; c < 4; c++) acc[r][c] = 0.f;

    for (int kc = 0; kc < 256; kc += 16) {
        float4 av = make_float4(0.f, 0.f, 0.f, 0.f);
        if (grow < N_NODES) av = *(const float4*)(x + (size_t)grow * 256 + kc + ak);
        As[ak + 0][arow] = av.x; As[ak + 1][arow] = av.y;
        As[ak + 2][arow] = av.z; As[ak + 3][arow] = av.w;
        const float4* Wp = (const float4*)(W1 + kc * 128);
        ((float4*)Bs)[tid]       = Wp[tid];
        ((float4*)Bs)[tid + 256] = Wp[tid + 256];
        __syncthreads();
#pragma unroll
        for (int k = 0; k < 16; k++) {
            float4 b   = *(const float4*)&Bs[k][tc << 2];
            float4 alo = *(const float4*)&As[k][tr << 3];
            float4 ahi = *(const float4*)&As[k][(tr << 3) + 4];
            float a[8] = {alo.x, alo.y, alo.z, alo.w, ahi.x, ahi.y, ahi.z, ahi.w};
#pragma unroll
            for (int r = 0; r < 8; r++) {
                acc[r][0] = fmaf(a[r], b.x, acc[r][0]);
                acc[r][1] = fmaf(a[r], b.y, acc[r][1]);
                acc[r][2] = fmaf(a[r], b.z, acc[r][2]);
                acc[r][3] = fmaf(a[r], b.w, acc[r][3]);
            }
        }
        __syncthreads();
    }
#pragma unroll
    for (int r = 0; r < 8; r++) {
        int row = brow + (tr << 3) + r;
        if (row < N_NODES) {
            float dv = g_dinv[row];
            float4 o = make_float4(acc[r][0] * dv, acc[r][1] * dv,
                                   acc[r][2] * dv, acc[r][3] * dv);
            *(float4*)&g_hs1[row * 128 + (tc << 2)] = o;
        }
    }
}

// ---------------------------------------------------------------------------
// Scatter layer 1: one warp per edge. Lane handles floats {lane, lane+32,
// lane+64, lane+96} — every load and every red instruction is a fully
// coalesced 128B transaction. acc1[dst] += hs1[src].
__global__ __launch_bounds__(256) void scatter1_kernel(const int* __restrict__ ei) {
    long long gtid = (long long)blockIdx.x * blockDim.x + threadIdx.x;
    int e = (int)(gtid >> 5);
    int lane = threadIdx.x & 31;
    if (e >= N_EDGES) return;
    int s = ei[e];
    int d = ei[N_EDGES + e];
    const float* src = &g_hs1[s * 128 + lane];
    float* dst = &g_acc1[d * 128 + lane];
#pragma unroll
    for (int i = 0; i < 4; i++) {
        atomicAdd(dst + 32 * i, src[32 * i]);
    }
}

// ---------------------------------------------------------------------------
// Finalize layer 1 + fused GEMM2: one warp per node.
// h = relu(dinv*(acc1 + hs1) + b1);  hs2 = dinv * (h @ W2)
__global__ __launch_bounds__(256) void finalize1_kernel(const float* __restrict__ b1,
                                                        const float* __restrict__ W2) {
    int w = (blockIdx.x * blockDim.x + threadIdx.x) >> 5;
    int lane = threadIdx.x & 31;
    if (w >= N_NODES) return;
    float dv = g_dinv[w];
    int off = w * 128 + (lane << 2);
    float4 a  = *(const float4*)&g_acc1[off];
    float4 h4 = *(const float4*)&g_hs1[off];
    float4 bb = *(const float4*)&b1[lane << 2];
    float hv[4];
    hv[0] = fmaxf(fmaf(dv, a.x + h4.x, bb.x), 0.f);
    hv[1] = fmaxf(fmaf(dv, a.y + h4.y, bb.y), 0.f);
    hv[2] = fmaxf(fmaf(dv, a.z + h4.z, bb.z), 0.f);
    hv[3] = fmaxf(fmaf(dv, a.w + h4.w, bb.w), 0.f);

    float p[8];
#pragma unroll
    for (int j = 0; j < 8; j++) p[j] = 0.f;
    const float* w2 = W2 + (lane << 2) * 8;   // W2 row-major [128][8]
#pragma unroll
    for (int c = 0; c < 4; c++)
#pragma unroll
        for (int j = 0; j < 8; j++) p[j] = fmaf(hv[c], w2[c * 8 + j], p[j]);

#pragma unroll
    for (int offx = 16; offx > 0; offx >>= 1)
#pragma unroll
        for (int j = 0; j < 8; j++) p[j] += __shfl_xor_sync(0xffffffffu, p[j], offx);

    if (lane == 0) {
#pragma unroll
        for (int j = 0; j < 8; j++) g_hs2[w * 8 + j] = dv * p[j];
    }
}

// ---------------------------------------------------------------------------
// Scatter layer 2: one thread per (edge, feature j of 8). Consecutive
// threads hit consecutive floats of the same edge row -> coalesced.
__global__ __launch_bounds__(256) void scatter2_kernel(const int* __restrict__ ei) {
    long long idx = (long long)blockIdx.x * blockDim.x + threadIdx.x;
    if (idx >= (long long)N_EDGES * 8) return;
    int e = (int)(idx >> 3), j = (int)(idx & 7);
    int s = ei[e];
    int d = ei[N_EDGES + e];
    atomicAdd(&g_acc2[d * 8 + j], g_hs2[s * 8 + j]);
}

__global__ __launch_bounds__(256) void finalize2_kernel(const float* __restrict__ b2) {
    int idx = blockIdx.x * blockDim.x + threadIdx.x;
    if (idx >= N_NODES * 2) return;
    int i = idx >> 1, part = idx & 1;
    float dv = g_dinv[i];
    int off = i * 8 + part * 4;
    float4 a = *(const float4*)&g_acc2[off];
    float4 h = *(const float4*)&g_hs2[off];
    float4 bb = *(const float4*)&b2[part * 4];
    float4 z;
    z.x = fmaf(dv, a.x + h.x, bb.x);
    z.y = fmaf(dv, a.y + h.y, bb.y);
    z.z = fmaf(dv, a.z + h.z, bb.z);
    z.w = fmaf(dv, a.w + h.w, bb.w);
    *(float4*)&g_z[off] = z;
}

// ---------------------------------------------------------------------------
// score[e] = sum_j z[a,j]*z[b,j] over concat(pos, neg)
__global__ __launch_bounds__(256) void score_kernel(const int* __restrict__ pos,
                                                    const int* __restrict__ neg,
                                                    float* __restrict__ out) {
    int e = blockIdx.x * blockDim.x + threadIdx.x;
    if (e >= 2 * N_PE) return;
    int ia, ib;
    if (e < N_PE) { ia = pos[e]; ib = pos[N_PE + e]; }
    else          { int t = e - N_PE; ia = neg[t]; ib = neg[N_PE + t]; }
    float4 za0 = *(const float4*)&g_z[ia * 8];
    float4 za1 = *(const float4*)&g_z[ia * 8 + 4];
    float4 zb0 = *(const float4*)&g_z[ib * 8];
    float4 zb1 = *(const float4*)&g_z[ib * 8 + 4];
    out[e] = za0.x * zb0.x + za0.y * zb0.y + za0.z * zb0.z + za0.w * zb0.w
           + za1.x * zb1.x + za1.y * zb1.y + za1.z * zb1.z + za1.w * zb1.w;
}

// ---------------------------------------------------------------------------
extern "C" void kernel_launch(void* const* d_in, const int* in_sizes, int n_in,
                              void* d_out, int out_size) {
    const float* x   = (const float*)d_in[0];
    const int*   ei  = (const int*)d_in[1];
    const int*   pos = (const int*)d_in[2];
    const int*   neg = (const int*)d_in[3];
    const float* W1  = (const float*)d_in[4];
    const float* b1  = (const float*)d_in[5];
    const float* W2  = (const float*)d_in[6];
    const float* b2  = (const float*)d_in[7];
    float* out = (float*)d_out;

    zero_kernel<<<2048, 256>>>();
    deg_kernel<<<N_EDGES / 256, 256>>>(ei + N_EDGES);
    dinv_kernel<<<(N_NODES + 255) / 256, 256>>>();
    gemm1_kernel<<<(N_NODES + 63) / 64, 256>>>(x, W1);
    scatter1_kernel<<<(N_EDGES * 32) / 256, 256>>>(ei);
    finalize1_kernel<<<(N_NODES * 32 + 255) / 256, 256>>>(b1, W2);
    scatter2_kernel<<<(int)(((long long)N_EDGES * 8 + 255) / 256), 256>>>(ei);
    finalize2_kernel<<<(N_NODES * 2 + 255) / 256, 256>>>(b2);
    score_kernel<<<(2 * N_PE + 255) / 256, 256>>>(pos, neg, out);
}

// round 10
// speedup vs baseline: 1.4004x; 1.4004x over previous
#include <cuda_runtime.h>

#define N_NODES 100000
#define N_EDGES 1600000
#define N_PE    200000
#define F1 128
#define F2 8
#define SCAN_B 1024
#define N_SCAN_BLK ((N_NODES + SCAN_B - 1) / SCAN_B)   // 98

// Scratch (static device globals — no allocation allowed)
__device__ __align__(16) float g_hs1[N_NODES * F1];   // dinv-scaled x@W1
__device__ __align__(16) float g_hs2[N_NODES * F2];   // dinv-scaled h@W2
__device__ __align__(16) float g_z[N_NODES * F2];     // layer-2 output
__device__ __align__(16) float g_dinv[N_NODES];
__device__ __align__(16) int   g_deg[N_NODES];
__device__ __align__(16) int   g_row_start[N_NODES];  // exclusive prefix of deg
__device__ __align__(16) int   g_cursor[N_NODES];     // fill cursors
__device__ __align__(16) int   g_csr_src[N_EDGES];    // src grouped by dst
__device__ __align__(16) int   g_bsum[N_SCAN_BLK];
__device__ __align__(16) int   g_boff[N_SCAN_BLK];

// ---------------------------------------------------------------------------
__global__ __launch_bounds__(256) void zero_deg_kernel() {
    int i = blockIdx.x * blockDim.x + threadIdx.x;
    if (i < N_NODES) g_deg[i] = 0;
}

__global__ __launch_bounds__(256) void deg_kernel(const int* __restrict__ dst) {
    int e = blockIdx.x * blockDim.x + threadIdx.x;
    if (e < N_EDGES) atomicAdd(&g_deg[dst[e]], 1);
}

__global__ __launch_bounds__(256) void dinv_kernel() {
    int i = blockIdx.x * blockDim.x + threadIdx.x;
    if (i < N_NODES) g_dinv[i] = rsqrtf((float)g_deg[i] + 1.0f);
}

// --- prefix sum of g_deg -> g_row_start (exclusive), 3 phases ---------------
__global__ __launch_bounds__(SCAN_B) void scan1_kernel() {
    __shared__ int s[SCAN_B];
    int tid = threadIdx.x;
    int i = blockIdx.x * SCAN_B + tid;
    int v = (i < N_NODES) ? g_deg[i] : 0;
    s[tid] = v;
    __syncthreads();
#pragma unroll
    for (int off = 1; off < SCAN_B; off <<= 1) {
        int t = (tid >= off) ? s[tid - off] : 0;
        __syncthreads();
        s[tid] += t;
        __syncthreads();
    }
    if (i < N_NODES) g_row_start[i] = s[tid] - v;   // exclusive within block
    if (tid == SCAN_B - 1) g_bsum[blockIdx.x] = s[tid];
}

__global__ __launch_bounds__(128) void scan2_kernel() {
    __shared__ int s[128];
    int tid = threadIdx.x;
    int v = (tid < N_SCAN_BLK) ? g_bsum[tid] : 0;
    s[tid] = v;
    __syncthreads();
#pragma unroll
    for (int off = 1; off < 128; off <<= 1) {
        int t = (tid >= off) ? s[tid - off] : 0;
        __syncthreads();
        s[tid] += t;
        __syncthreads();
    }
    if (tid < N_SCAN_BLK) g_boff[tid] = s[tid] - v; // exclusive block offsets
}

__global__ __launch_bounds__(SCAN_B) void scan3_kernel() {
    int i = blockIdx.x * SCAN_B + threadIdx.x;
    if (i < N_NODES) {
        int r = g_row_start[i] + g_boff[blockIdx.x];
        g_row_start[i] = r;
        g_cursor[i] = r;
    }
}

__global__ __launch_bounds__(256) void fill_kernel(const int* __restrict__ ei) {
    int e = blockIdx.x * blockDim.x + threadIdx.x;
    if (e >= N_EDGES) return;
    int s = ei[e];
    int d = ei[N_EDGES + e];
    int pos = atomicAdd(&g_cursor[d], 1);
    g_csr_src[pos] = s;
}

// ---------------------------------------------------------------------------
// GEMM1: hs1[i,:] = dinv[i] * (x[i,:] @ W1)   (M=100000, K=256, N=128)
__global__ __launch_bounds__(256) void gemm1_kernel(const float* __restrict__ x,
                                                    const float* __restrict__ W1) {
    __shared__ float As[16][64];    // transposed A chunk
    __shared__ float Bs[16][128];
    const int tid  = threadIdx.x;
    const int tr   = tid >> 5;
    const int tc   = tid & 31;
    const int brow = blockIdx.x * 64;
    const int arow = tid >> 2;
    const int ak   = (tid & 3) << 2;
    const int grow = brow + arow;

    float acc[8][4];
#pragma unroll
    for (int r = 0; r < 8; r++)
#pragma unroll
        for (int c = 0; c < 4; c++) acc[r][c] = 0.f;

    for (int kc = 0; kc < 256; kc += 16) {
        float4 av = make_float4(0.f, 0.f, 0.f, 0.f);
        if (grow < N_NODES) av = *(const float4*)(x + (size_t)grow * 256 + kc + ak);
        As[ak + 0][arow] = av.x; As[ak + 1][arow] = av.y;
        As[ak + 2][arow] = av.z; As[ak + 3][arow] = av.w;
        const float4* Wp = (const float4*)(W1 + kc * 128);
        ((float4*)Bs)[tid]       = Wp[tid];
        ((float4*)Bs)[tid + 256] = Wp[tid + 256];
        __syncthreads();
#pragma unroll
        for (int k = 0; k < 16; k++) {
            float4 b   = *(const float4*)&Bs[k][tc << 2];
            float4 alo = *(const float4*)&As[k][tr << 3];
            float4 ahi = *(const float4*)&As[k][(tr << 3) + 4];
            float a[8] = {alo.x, alo.y, alo.z, alo.w, ahi.x, ahi.y, ahi.z, ahi.w};
#pragma unroll
            for (int r = 0; r < 8; r++) {
                acc[r][0] = fmaf(a[r], b.x, acc[r][0]);
                acc[r][1] = fmaf(a[r], b.y, acc[r][1]);
                acc[r][2] = fmaf(a[r], b.z, acc[r][2]);
                acc[r][3] = fmaf(a[r], b.w, acc[r][3]);
            }
        }
        __syncthreads();
    }
#pragma unroll
    for (int r = 0; r < 8; r++) {
        int row = brow + (tr << 3) + r;
        if (row < N_NODES) {
            float dv = g_dinv[row];
            float4 o = make_float4(acc[r][0] * dv, acc[r][1] * dv,
                                   acc[r][2] * dv, acc[r][3] * dv);
            *(float4*)&g_hs1[row * 128 + (tc << 2)] = o;
        }
    }
}

// ---------------------------------------------------------------------------
// Fused gather + finalize layer 1 + GEMM2: one warp per node.
// acc = hs1[node] + sum_{s in in(node)} hs1[s]        (self-loop + neighbors)
// h   = relu(dinv*acc + b1);  hs2[node] = dinv * (h @ W2)
__global__ __launch_bounds__(256) void gather1_kernel(const float* __restrict__ b1,
                                                      const float* __restrict__ W2) {
    int node = (blockIdx.x * blockDim.x + threadIdx.x) >> 5;
    int lane = threadIdx.x & 31;
    if (node >= N_NODES) return;
    float dv = g_dinv[node];
    int beg = g_row_start[node];
    int end = beg + g_deg[node];

    // self-loop row
    float4 acc = *(const float4*)&g_hs1[node * 128 + (lane << 2)];

    int k = beg;
    for (; k + 1 < end; k += 2) {          // unroll 2 for MLP
        int s0 = g_csr_src[k];
        int s1 = g_csr_src[k + 1];
        float4 v0 = *(const float4*)&g_hs1[s0 * 128 + (lane << 2)];
        float4 v1 = *(const float4*)&g_hs1[s1 * 128 + (lane << 2)];
        acc.x += v0.x + v1.x; acc.y += v0.y + v1.y;
        acc.z += v0.z + v1.z; acc.w += v0.w + v1.w;
    }
    if (k < end) {
        int s0 = g_csr_src[k];
        float4 v0 = *(const float4*)&g_hs1[s0 * 128 + (lane << 2)];
        acc.x += v0.x; acc.y += v0.y; acc.z += v0.z; acc.w += v0.w;
    }

    float4 bb = *(const float4*)&b1[lane << 2];
    float hv[4];
    hv[0] = fmaxf(fmaf(dv, acc.x, bb.x), 0.f);
    hv[1] = fmaxf(fmaf(dv, acc.y, bb.y), 0.f);
    hv[2] = fmaxf(fmaf(dv, acc.z, bb.z), 0.f);
    hv[3] = fmaxf(fmaf(dv, acc.w, bb.w), 0.f);

    float p[8];
#pragma unroll
    for (int j = 0; j < 8; j++) p[j] = 0.f;
    const float* w2 = W2 + (lane << 2) * 8;   // W2 row-major [128][8]
#pragma unroll
    for (int c = 0; c < 4; c++)
#pragma unroll
        for (int j = 0; j < 8; j++) p[j] = fmaf(hv[c], w2[c * 8 + j], p[j]);

#pragma unroll
    for (int offx = 16; offx > 0; offx >>= 1)
#pragma unroll
        for (int j = 0; j < 8; j++) p[j] += __shfl_xor_sync(0xffffffffu, p[j], offx);

    if (lane == 0) {
#pragma unroll
        for (int j = 0; j < 8; j++) g_hs2[node * 8 + j] = dv * p[j];
    }
}

// ---------------------------------------------------------------------------
// Fused gather + finalize layer 2: one warp per node, 4 edge slots x 8 feats.
// z[node] = dinv*(sum_in hs2[s] + hs2[node]) + b2
__global__ __launch_bounds__(256) void gather2_kernel(const float* __restrict__ b2) {
    int node = (blockIdx.x * blockDim.x + threadIdx.x) >> 5;
    int lane = threadIdx.x & 31;
    if (node >= N_NODES) return;
    float dv = g_dinv[node];
    int beg = g_row_start[node];
    int end = beg + g_deg[node];
    int slot = lane >> 3;     // 0..3
    int j    = lane & 7;      // feature

    float acc = 0.f;
    for (int k = beg + slot; k < end; k += 4) {
        int s = g_csr_src[k];
        acc += g_hs2[s * 8 + j];
    }
    // reduce across the 4 slots (lanes j, j+8, j+16, j+24)
    acc += __shfl_xor_sync(0xffffffffu, acc, 8);
    acc += __shfl_xor_sync(0xffffffffu, acc, 16);

    if (lane < 8) {
        float z = fmaf(dv, acc + g_hs2[node * 8 + lane], b2[lane]);
        g_z[node * 8 + lane] = z;
    }
}

// ---------------------------------------------------------------------------
// score[e] = sum_j z[a,j]*z[b,j] over concat(pos, neg)
__global__ __launch_bounds__(256) void score_kernel(const int* __restrict__ pos,
                                                    const int* __restrict__ neg,
                                                    float* __restrict__ out) {
    int e = blockIdx.x * blockDim.x + threadIdx.x;
    if (e >= 2 * N_PE) return;
    int ia, ib;
    if (e < N_PE) { ia = pos[e]; ib = pos[N_PE + e]; }
    else          { int t = e - N_PE; ia = neg[t]; ib = neg[N_PE + t]; }
    float4 za0 = *(const float4*)&g_z[ia * 8];
    float4 za1 = *(const float4*)&g_z[ia * 8 + 4];
    float4 zb0 = *(const float4*)&g_z[ib * 8];
    float4 zb1 = *(const float4*)&g_z[ib * 8 + 4];
    out[e] = za0.x * zb0.x + za0.y * zb0.y + za0.z * zb0.z + za0.w * zb0.w
           + za1.x * zb1.x + za1.y * zb1.y + za1.z * zb1.z + za1.w * zb1.w;
}

// ---------------------------------------------------------------------------
extern "C" void kernel_launch(void* const* d_in, const int* in_sizes, int n_in,
                              void* d_out, int out_size) {
    const float* x   = (const float*)d_in[0];
    const int*   ei  = (const int*)d_in[1];
    const int*   pos = (const int*)d_in[2];
    const int*   neg = (const int*)d_in[3];
    const float* W1  = (const float*)d_in[4];
    const float* b1  = (const float*)d_in[5];
    const float* W2  = (const float*)d_in[6];
    const float* b2  = (const float*)d_in[7];
    float* out = (float*)d_out;

    zero_deg_kernel<<<(N_NODES + 255) / 256, 256>>>();
    deg_kernel<<<N_EDGES / 256, 256>>>(ei + N_EDGES);
    dinv_kernel<<<(N_NODES + 255) / 256, 256>>>();
    scan1_kernel<<<N_SCAN_BLK, SCAN_B>>>();
    scan2_kernel<<<1, 128>>>();
    scan3_kernel<<<N_SCAN_BLK, SCAN_B>>>();
    fill_kernel<<<N_EDGES / 256, 256>>>(ei);
    gemm1_kernel<<<(N_NODES + 63) / 64, 256>>>(x, W1);
    gather1_kernel<<<(N_NODES * 32 + 255) / 256, 256>>>(b1, W2);
    gather2_kernel<<<(N_NODES * 32 + 255) / 256, 256>>>(b2);
    score_kernel<<<(2 * N_PE + 255) / 256, 256>>>(pos, neg, out);
}